// round 3
// baseline (speedup 1.0000x reference)
#include <cuda_runtime.h>
#include <cuda_bf16.h>
#include <cstdint>

#define BDIM   8192
#define IN_F   512
#define OUT_F  1024
#define K_TOT  2560            // [S(512) | Z(1024) | Z(1024)]
#define BM 128
#define BN 128
#define BK 64                  // 64 bf16 = 128B swizzled row
#define NIT (K_TOT/BK)         // 40
#define STAGE_BYTES (BM*BK*2)  // 16384 (A) ; same for B
#define SM_B_OFF (3*STAGE_BYTES)
#define SMEM_DYN (6*STAGE_BYTES + 1024)

__device__ __align__(16) __nv_bfloat16 g_A[(size_t)BDIM * K_TOT];   // 41.9 MB
__device__ __align__(16) __nv_bfloat16 g_B[(size_t)OUT_F * K_TOT];  // 5.2 MB

__device__ __forceinline__ uint32_t smem_u32(const void* p){
    uint32_t a;
    asm("{ .reg .u64 t; cvta.to.shared.u64 t, %1; cvt.u32.u64 %0, t; }":"=r"(a):"l"(p));
    return a;
}
__device__ __forceinline__ uint64_t gaddr(const void* p){
    uint64_t a; asm("cvta.to.global.u64 %0, %1;":"=l"(a):"l"(p)); return a;
}
__device__ __forceinline__ void cp16(uint32_t dst, uint64_t src){
    asm volatile("cp.async.cg.shared.global [%0], [%1], 16;"::"r"(dst),"l"(src));
}
#define LDSM4(r0,r1,r2,r3,addr) \
    asm volatile("ldmatrix.sync.aligned.m8n8.x4.shared.b16 {%0,%1,%2,%3}, [%4];" \
        : "=r"(r0),"=r"(r1),"=r"(r2),"=r"(r3) : "r"(addr))
#define MMA(d,a,b0,b1) \
    asm volatile("mma.sync.aligned.m16n8k16.row.col.f32.bf16.bf16.f32 " \
        "{%0,%1,%2,%3}, {%4,%5,%6,%7}, {%8,%9}, {%0,%1,%2,%3};" \
        : "+f"((d)[0]),"+f"((d)[1]),"+f"((d)[2]),"+f"((d)[3]) \
        : "r"((a)[0]),"r"((a)[1]),"r"((a)[2]),"r"((a)[3]),"r"(b0),"r"(b1))

// ---------------- prep A: [spk | z | z] bf16 (exact: values 0/1) ----------------
__global__ void prep_A(const float* __restrict__ spk, const float* __restrict__ zin){
    int t = blockIdx.x*blockDim.x + threadIdx.x;
    const int SPK_T = BDIM*(IN_F/4);
    if (t < SPK_T){
        int row = t>>7, c = (t&127)<<2;
        float4 f = *reinterpret_cast<const float4*>(spk + (size_t)row*IN_F + c);
        uint2 pk;
        pk.x = (uint32_t)__bfloat16_as_ushort(__float2bfloat16(f.x)) |
               ((uint32_t)__bfloat16_as_ushort(__float2bfloat16(f.y))<<16);
        pk.y = (uint32_t)__bfloat16_as_ushort(__float2bfloat16(f.z)) |
               ((uint32_t)__bfloat16_as_ushort(__float2bfloat16(f.w))<<16);
        *reinterpret_cast<uint2*>(g_A + (size_t)row*K_TOT + c) = pk;
    } else {
        int t2 = t - SPK_T;
        if (t2 < BDIM*(OUT_F/4)){
            int row = t2>>8, c = (t2&255)<<2;
            float4 f = *reinterpret_cast<const float4*>(zin + (size_t)row*OUT_F + c);
            uint2 pk;
            pk.x = (uint32_t)__bfloat16_as_ushort(__float2bfloat16(f.x)) |
                   ((uint32_t)__bfloat16_as_ushort(__float2bfloat16(f.y))<<16);
            pk.y = (uint32_t)__bfloat16_as_ushort(__float2bfloat16(f.z)) |
                   ((uint32_t)__bfloat16_as_ushort(__float2bfloat16(f.w))<<16);
            size_t base = (size_t)row*K_TOT + IN_F + c;
            *reinterpret_cast<uint2*>(g_A + base)         = pk;
            *reinterpret_cast<uint2*>(g_A + base + OUT_F) = pk;
        }
    }
}

// ---------------- prep B: [Win | Wrec_hi | Wrec_lo] ----------------
__global__ void prep_B(const float* __restrict__ win, const float* __restrict__ wrec){
    int t = blockIdx.x*blockDim.x + threadIdx.x;
    const int WIN_T = OUT_F*IN_F;
    if (t < WIN_T){
        int o = t>>9, c = t&511;
        g_B[(size_t)o*K_TOT + c] = __float2bfloat16(win[t]);
    } else {
        int t2 = t - WIN_T;
        if (t2 < OUT_F*OUT_F){
            int o = t2>>10, c = t2&1023;
            float w = wrec[t2];
            __nv_bfloat16 h = __float2bfloat16(w);
            __nv_bfloat16 l = __float2bfloat16(w - __bfloat162float(h));
            size_t base = (size_t)o*K_TOT;
            g_B[base + 512 + c]  = h;
            g_B[base + 1536 + c] = l;
        }
    }
}

// 128-row x 128B-row tile loader, XOR-8 swizzle on 16B chunks
__device__ __forceinline__ void load_stage(uint32_t sA, uint32_t sB,
                                           uint64_t ga, uint64_t gb, int tid){
    const uint64_t gs = (uint64_t)K_TOT*2;
#pragma unroll
    for (int j = 0; j < 4; j++){
        int ch = tid + j*256, r = ch>>3, c = ch&7;
        uint32_t sw = (uint32_t)(r*128 + ((c ^ (r&7))<<4));
        cp16(sA + sw, ga + (uint64_t)r*gs + c*16);
    }
#pragma unroll
    for (int j = 0; j < 4; j++){
        int ch = tid + j*256, r = ch>>3, c = ch&7;
        uint32_t sw = (uint32_t)(r*128 + ((c ^ (r&7))<<4));
        cp16(sB + sw, gb + (uint64_t)r*gs + c*16);
    }
}

__global__ void __launch_bounds__(256, 2) lsnn_gemm(
    const float* __restrict__ vin, const float* __restrict__ iin,
    const float* __restrict__ bin, float* __restrict__ out)
{
    extern __shared__ char smem_raw[];
    const uint32_t s0 = (smem_u32(smem_raw) + 1023u) & ~1023u;
    const int tid = threadIdx.x, wid = tid>>5, lane = tid&31;
    const int wm = wid & 3, wn = wid >> 2;          // 4x2 warp grid: 32m x 64n each
    const int nt = blockIdx.x & 7, mt = blockIdx.x >> 3;
    const int m0 = mt*BM, n0 = nt*BN;

    const uint64_t gA0 = gaddr(g_A) + (uint64_t)m0*K_TOT*2;
    const uint64_t gB0 = gaddr(g_B) + (uint64_t)n0*K_TOT*2;

    float acc[2][8][4];
#pragma unroll
    for (int a = 0; a < 2; a++)
#pragma unroll
        for (int b = 0; b < 8; b++)
#pragma unroll
            for (int c = 0; c < 4; c++) acc[a][b][c] = 0.0f;

    // prologue: stages 0,1
#pragma unroll
    for (int i = 0; i < 2; i++){
        load_stage(s0 + i*STAGE_BYTES, s0 + SM_B_OFF + i*STAGE_BYTES,
                   gA0 + (uint64_t)i*BK*2, gB0 + (uint64_t)i*BK*2, tid);
        asm volatile("cp.async.commit_group;":::"memory");
    }

    const int rA = lane & 15, hi = lane >> 4;

    for (int i = 0; i < NIT; i++){
        if (i + 2 < NIT){
            int s = (i+2)%3;
            load_stage(s0 + s*STAGE_BYTES, s0 + SM_B_OFF + s*STAGE_BYTES,
                       gA0 + (uint64_t)(i+2)*BK*2, gB0 + (uint64_t)(i+2)*BK*2, tid);
        }
        asm volatile("cp.async.commit_group;":::"memory");
        asm volatile("cp.async.wait_group 2;":::"memory");
        __syncthreads();

        const uint32_t aB = s0 + (i%3)*STAGE_BYTES;
        const uint32_t bB = s0 + SM_B_OFF + (i%3)*STAGE_BYTES;
#pragma unroll
        for (int kk = 0; kk < 4; kk++){
            uint32_t a[2][4], b[4][4];
            const int ch = kk*2 + hi;
#pragma unroll
            for (int t = 0; t < 2; t++){
                int r = wm*32 + t*16 + rA;
                LDSM4(a[t][0],a[t][1],a[t][2],a[t][3],
                      aB + r*128 + ((ch ^ (r&7))<<4));
            }
#pragma unroll
            for (int t = 0; t < 4; t++){
                int r = wn*64 + t*16 + rA;
                LDSM4(b[t][0],b[t][1],b[t][2],b[t][3],
                      bB + r*128 + ((ch ^ (r&7))<<4));
            }
#pragma unroll
            for (int t = 0; t < 2; t++)
#pragma unroll
                for (int n8 = 0; n8 < 8; n8++)
                    MMA(acc[t][n8], a[t], b[n8>>1][n8&1], b[n8>>1][(n8&1)+2]);
        }
        __syncthreads();
    }

    // ---- fused LSNN epilogue (bit-exact state math; rn intrinsics, no FMA) ----
    const float C_VD = (float)(0.001*100.0);          // 0.1
    const float C_ID = (float)(0.001*(-200.0));       // -0.2
    const float C_BD = (float)(0.001*(1.0/800.0));    // 1.25e-6
    const float C_BJ = (float)((1.0/800.0)*1.8);      // 0.00225
    const size_t PS = (size_t)BDIM*OUT_F;

#pragma unroll
    for (int t = 0; t < 2; t++){
#pragma unroll
        for (int rr = 0; rr < 2; rr++){
            const size_t row = (size_t)(m0 + wm*32 + t*16 + rr*8 + (lane>>2));
            const float* vr = vin + row*OUT_F;
            const float* ir = iin + row*OUT_F;
            const float* br = bin + row*OUT_F;
            float* oz = out + row*OUT_F;
#pragma unroll
            for (int n8 = 0; n8 < 8; n8++){
                const int c = n0 + wn*64 + n8*8 + 2*(lane&3);
                float2 v2 = *reinterpret_cast<const float2*>(vr + c);
                float2 i2 = *reinterpret_cast<const float2*>(ir + c);
                float2 b2 = *reinterpret_cast<const float2*>(br + c);
                float vv[2] = {v2.x, v2.y}, ii[2] = {i2.x, i2.y}, bb[2] = {b2.x, b2.y};
                float zz[2], vo[2], io[2], bo[2];
#pragma unroll
                for (int e = 0; e < 2; e++){
                    float vd = __fadd_rn(vv[e], __fmul_rn(C_VD, __fadd_rn(ii[e], -vv[e])));
                    float id = __fadd_rn(ii[e], __fmul_rn(C_ID, ii[e]));
                    float bd = __fadd_rn(bb[e], __fmul_rn(C_BD, __fadd_rn(1.0f, -bb[e])));
                    float zn = (__fadd_rn(vd, -bd) > 0.0f) ? 1.0f : 0.0f;
                    zz[e] = zn;
                    vo[e] = (zn != 0.0f) ? 0.0f : vd;
                    io[e] = __fadd_rn(id, acc[t][n8][rr*2 + e]);
                    bo[e] = __fadd_rn(bd, __fmul_rn(zn, C_BJ));
                }
                *reinterpret_cast<float2*>(oz + c)        = make_float2(zz[0], zz[1]);
                *reinterpret_cast<float2*>(oz + PS + c)   = make_float2(vo[0], vo[1]);
                *reinterpret_cast<float2*>(oz + 2*PS + c) = make_float2(io[0], io[1]);
                *reinterpret_cast<float2*>(oz + 3*PS + c) = make_float2(bo[0], bo[1]);
            }
        }
    }
}

extern "C" void kernel_launch(void* const* d_in, const int* in_sizes, int n_in,
                              void* d_out, int out_size){
    const float* spikes = (const float*)d_in[0];
    const float* z      = (const float*)d_in[1];
    const float* v      = (const float*)d_in[2];
    const float* i_     = (const float*)d_in[3];
    const float* b      = (const float*)d_in[4];
    const float* win    = (const float*)d_in[5];
    const float* wrec   = (const float*)d_in[6];
    float* out = (float*)d_out;

    cudaFuncSetAttribute(lsnn_gemm, cudaFuncAttributeMaxDynamicSharedMemorySize, SMEM_DYN);

    prep_A<<<(BDIM*(IN_F/4) + BDIM*(OUT_F/4) + 255)/256, 256>>>(spikes, z);
    prep_B<<<(OUT_F*IN_F + OUT_F*OUT_F + 255)/256, 256>>>(win, wrec);
    lsnn_gemm<<<(BDIM/BM)*(OUT_F/BN), 256, SMEM_DYN>>>(v, i_, b, out);
}

// round 4
// speedup vs baseline: 1.3598x; 1.3598x over previous
#include <cuda_runtime.h>
#include <cuda_fp16.h>
#include <cstdint>

#define BDIM   8192
#define IN_F   512
#define OUT_F  1024
#define K_TOT  1536            // [S(512) | Z(1024)], fp16 weights single-pass
#define BM 128
#define BN 128
#define BK 64                  // 64 fp16 = 128B swizzled row
#define NIT (K_TOT/BK)         // 24
#define STAGE_BYTES (BM*BK*2)  // 16384 (A) ; same for B
#define SM_B_OFF (3*STAGE_BYTES)
#define SMEM_DYN (6*STAGE_BYTES + 1024)

__device__ __align__(16) __half g_A[(size_t)BDIM * K_TOT];   // 25.2 MB
__device__ __align__(16) __half g_B[(size_t)OUT_F * K_TOT];  // 3.1 MB

__device__ __forceinline__ uint32_t smem_u32(const void* p){
    uint32_t a;
    asm("{ .reg .u64 t; cvta.to.shared.u64 t, %1; cvt.u32.u64 %0, t; }":"=r"(a):"l"(p));
    return a;
}
__device__ __forceinline__ uint64_t gaddr(const void* p){
    uint64_t a; asm("cvta.to.global.u64 %0, %1;":"=l"(a):"l"(p)); return a;
}
__device__ __forceinline__ void cp16(uint32_t dst, uint64_t src){
    asm volatile("cp.async.cg.shared.global [%0], [%1], 16;"::"r"(dst),"l"(src));
}
#define LDSM4(r0,r1,r2,r3,addr) \
    asm volatile("ldmatrix.sync.aligned.m8n8.x4.shared.b16 {%0,%1,%2,%3}, [%4];" \
        : "=r"(r0),"=r"(r1),"=r"(r2),"=r"(r3) : "r"(addr))
#define MMA(d,a,b0,b1) \
    asm volatile("mma.sync.aligned.m16n8k16.row.col.f32.f16.f16.f32 " \
        "{%0,%1,%2,%3}, {%4,%5,%6,%7}, {%8,%9}, {%0,%1,%2,%3};" \
        : "+f"((d)[0]),"+f"((d)[1]),"+f"((d)[2]),"+f"((d)[3]) \
        : "r"((a)[0]),"r"((a)[1]),"r"((a)[2]),"r"((a)[3]),"r"(b0),"r"(b1))

// ---------------- prep A: [spk | z] fp16 (exact: values 0/1) ----------------
__global__ void prep_A(const float* __restrict__ spk, const float* __restrict__ zin){
    int t = blockIdx.x*blockDim.x + threadIdx.x;
    const int SPK_T = BDIM*(IN_F/4);
    if (t < SPK_T){
        int row = t>>7, c = (t&127)<<2;
        float4 f = *reinterpret_cast<const float4*>(spk + (size_t)row*IN_F + c);
        uint2 pk;
        pk.x = (uint32_t)__half_as_ushort(__float2half_rn(f.x)) |
               ((uint32_t)__half_as_ushort(__float2half_rn(f.y))<<16);
        pk.y = (uint32_t)__half_as_ushort(__float2half_rn(f.z)) |
               ((uint32_t)__half_as_ushort(__float2half_rn(f.w))<<16);
        *reinterpret_cast<uint2*>(g_A + (size_t)row*K_TOT + c) = pk;
    } else {
        int t2 = t - SPK_T;
        if (t2 < BDIM*(OUT_F/4)){
            int row = t2>>8, c = (t2&255)<<2;
            float4 f = *reinterpret_cast<const float4*>(zin + (size_t)row*OUT_F + c);
            uint2 pk;
            pk.x = (uint32_t)__half_as_ushort(__float2half_rn(f.x)) |
                   ((uint32_t)__half_as_ushort(__float2half_rn(f.y))<<16);
            pk.y = (uint32_t)__half_as_ushort(__float2half_rn(f.z)) |
                   ((uint32_t)__half_as_ushort(__float2half_rn(f.w))<<16);
            *reinterpret_cast<uint2*>(g_A + (size_t)row*K_TOT + IN_F + c) = pk;
        }
    }
}

// ---------------- prep B: [Win_f16 | Wrec_f16] ----------------
__global__ void prep_B(const float* __restrict__ win, const float* __restrict__ wrec){
    int t = blockIdx.x*blockDim.x + threadIdx.x;
    const int WIN_T = OUT_F*IN_F;
    if (t < WIN_T){
        int o = t>>9, c = t&511;
        g_B[(size_t)o*K_TOT + c] = __float2half_rn(win[t]);
    } else {
        int t2 = t - WIN_T;
        if (t2 < OUT_F*OUT_F){
            int o = t2>>10, c = t2&1023;
            g_B[(size_t)o*K_TOT + IN_F + c] = __float2half_rn(wrec[t2]);
        }
    }
}

// 128-row x 128B-row tile loader, XOR-8 swizzle on 16B chunks
__device__ __forceinline__ void load_stage(uint32_t sA, uint32_t sB,
                                           uint64_t ga, uint64_t gb, int tid){
    const uint64_t gs = (uint64_t)K_TOT*2;
#pragma unroll
    for (int j = 0; j < 4; j++){
        int ch = tid + j*256, r = ch>>3, c = ch&7;
        uint32_t sw = (uint32_t)(r*128 + ((c ^ (r&7))<<4));
        cp16(sA + sw, ga + (uint64_t)r*gs + c*16);
    }
#pragma unroll
    for (int j = 0; j < 4; j++){
        int ch = tid + j*256, r = ch>>3, c = ch&7;
        uint32_t sw = (uint32_t)(r*128 + ((c ^ (r&7))<<4));
        cp16(sB + sw, gb + (uint64_t)r*gs + c*16);
    }
}

__global__ void __launch_bounds__(256, 2) lsnn_gemm(
    const float* __restrict__ vin, const float* __restrict__ iin,
    const float* __restrict__ bin, float* __restrict__ out)
{
    extern __shared__ char smem_raw[];
    const uint32_t s0 = (smem_u32(smem_raw) + 1023u) & ~1023u;
    const int tid = threadIdx.x, wid = tid>>5, lane = tid&31;
    const int wm = wid & 3, wn = wid >> 2;          // 4x2 warp grid: 32m x 64n each
    const int nt = blockIdx.x & 7, mt = blockIdx.x >> 3;
    const int m0 = mt*BM, n0 = nt*BN;

    const uint64_t gA0 = gaddr(g_A) + (uint64_t)m0*K_TOT*2;
    const uint64_t gB0 = gaddr(g_B) + (uint64_t)n0*K_TOT*2;

    float acc[2][8][4];
#pragma unroll
    for (int a = 0; a < 2; a++)
#pragma unroll
        for (int b = 0; b < 8; b++)
#pragma unroll
            for (int c = 0; c < 4; c++) acc[a][b][c] = 0.0f;

    // prologue: stages 0,1
#pragma unroll
    for (int i = 0; i < 2; i++){
        load_stage(s0 + i*STAGE_BYTES, s0 + SM_B_OFF + i*STAGE_BYTES,
                   gA0 + (uint64_t)i*BK*2, gB0 + (uint64_t)i*BK*2, tid);
        asm volatile("cp.async.commit_group;":::"memory");
    }

    const int rA = lane & 15, hi = lane >> 4;

    for (int i = 0; i < NIT; i++){
        if (i + 2 < NIT){
            int s = (i+2)%3;
            load_stage(s0 + s*STAGE_BYTES, s0 + SM_B_OFF + s*STAGE_BYTES,
                       gA0 + (uint64_t)(i+2)*BK*2, gB0 + (uint64_t)(i+2)*BK*2, tid);
        }
        asm volatile("cp.async.commit_group;":::"memory");
        asm volatile("cp.async.wait_group 2;":::"memory");
        __syncthreads();

        const uint32_t aB = s0 + (i%3)*STAGE_BYTES;
        const uint32_t bB = s0 + SM_B_OFF + (i%3)*STAGE_BYTES;
#pragma unroll
        for (int kk = 0; kk < 4; kk++){
            uint32_t a[2][4], b[4][4];
            const int ch = kk*2 + hi;
#pragma unroll
            for (int t = 0; t < 2; t++){
                int r = wm*32 + t*16 + rA;
                LDSM4(a[t][0],a[t][1],a[t][2],a[t][3],
                      aB + r*128 + ((ch ^ (r&7))<<4));
            }
#pragma unroll
            for (int t = 0; t < 4; t++){
                int r = wn*64 + t*16 + rA;
                LDSM4(b[t][0],b[t][1],b[t][2],b[t][3],
                      bB + r*128 + ((ch ^ (r&7))<<4));
            }
#pragma unroll
            for (int t = 0; t < 2; t++)
#pragma unroll
                for (int n8 = 0; n8 < 8; n8++)
                    MMA(acc[t][n8], a[t], b[n8>>1][n8&1], b[n8>>1][(n8&1)+2]);
        }
        __syncthreads();
    }

    // ---- fused LSNN epilogue (exact reference op order; rn intrinsics) ----
    const float C_VD = 0.1f;
    const float C_ID = -0.2f;
    const float C_BD = 1.25e-6f;
    const float C_BJ = 0.00225f;
    const size_t PS = (size_t)BDIM*OUT_F;

#pragma unroll
    for (int t = 0; t < 2; t++){
#pragma unroll
        for (int rr = 0; rr < 2; rr++){
            const size_t row = (size_t)(m0 + wm*32 + t*16 + rr*8 + (lane>>2));
            const float* vr = vin + row*OUT_F;
            const float* ir = iin + row*OUT_F;
            const float* br = bin + row*OUT_F;
            float* oz = out + row*OUT_F;
#pragma unroll
            for (int n8 = 0; n8 < 8; n8++){
                const int c = n0 + wn*64 + n8*8 + 2*(lane&3);
                float2 v2 = *reinterpret_cast<const float2*>(vr + c);
                float2 i2 = *reinterpret_cast<const float2*>(ir + c);
                float2 b2 = *reinterpret_cast<const float2*>(br + c);
                float vv[2] = {v2.x, v2.y}, ii[2] = {i2.x, i2.y}, bb[2] = {b2.x, b2.y};
                float zz[2], vo[2], io[2], bo[2];
#pragma unroll
                for (int e = 0; e < 2; e++){
                    float vd = __fadd_rn(vv[e], __fmul_rn(C_VD, __fadd_rn(ii[e], -vv[e])));
                    float id = __fadd_rn(ii[e], __fmul_rn(C_ID, ii[e]));
                    float bd = __fadd_rn(bb[e], __fmul_rn(C_BD, __fadd_rn(1.0f, -bb[e])));
                    float zn = (__fadd_rn(vd, -bd) > 0.0f) ? 1.0f : 0.0f;
                    zz[e] = zn;
                    vo[e] = (zn != 0.0f) ? 0.0f : vd;
                    io[e] = __fadd_rn(id, acc[t][n8][rr*2 + e]);
                    bo[e] = __fadd_rn(bd, __fmul_rn(zn, C_BJ));
                }
                *reinterpret_cast<float2*>(oz + c)        = make_float2(zz[0], zz[1]);
                *reinterpret_cast<float2*>(oz + PS + c)   = make_float2(vo[0], vo[1]);
                *reinterpret_cast<float2*>(oz + 2*PS + c) = make_float2(io[0], io[1]);
                *reinterpret_cast<float2*>(oz + 3*PS + c) = make_float2(bo[0], bo[1]);
            }
        }
    }
}

extern "C" void kernel_launch(void* const* d_in, const int* in_sizes, int n_in,
                              void* d_out, int out_size){
    const float* spikes = (const float*)d_in[0];
    const float* z      = (const float*)d_in[1];
    const float* v      = (const float*)d_in[2];
    const float* i_     = (const float*)d_in[3];
    const float* b      = (const float*)d_in[4];
    const float* win    = (const float*)d_in[5];
    const float* wrec   = (const float*)d_in[6];
    float* out = (float*)d_out;

    cudaFuncSetAttribute(lsnn_gemm, cudaFuncAttributeMaxDynamicSharedMemorySize, SMEM_DYN);

    prep_A<<<(BDIM*(IN_F/4) + BDIM*(OUT_F/4) + 255)/256, 256>>>(spikes, z);
    prep_B<<<(OUT_F*IN_F + OUT_F*OUT_F + 255)/256, 256>>>(win, wrec);
    lsnn_gemm<<<(BDIM/BM)*(OUT_F/BN), 256, SMEM_DYN>>>(v, i_, b, out);
}

// round 5
// speedup vs baseline: 1.4193x; 1.0438x over previous
#include <cuda_runtime.h>
#include <cuda_fp16.h>
#include <cstdint>

#define BDIM   8192
#define IN_F   512
#define OUT_F  1024
#define K_TOT  1536            // [S(512) | Z(1024)], fp16 weights single-pass
#define BM 128
#define BN 128
#define BK 64                  // 64 fp16 = 128B swizzled row
#define NIT (K_TOT/BK)         // 24
#define STAGE_BYTES (BM*BK*2)  // 16384
#define SM_B_OFF (3*STAGE_BYTES)
#define SMEM_DYN (6*STAGE_BYTES + 1024)

__device__ __align__(16) __half g_A[(size_t)BDIM * K_TOT];   // 25.2 MB
__device__ __align__(16) __half g_B[(size_t)OUT_F * K_TOT];  // 3.1 MB

__device__ __forceinline__ uint32_t smem_u32(const void* p){
    uint32_t a;
    asm("{ .reg .u64 t; cvta.to.shared.u64 t, %1; cvt.u32.u64 %0, t; }":"=r"(a):"l"(p));
    return a;
}
__device__ __forceinline__ uint64_t gaddr(const void* p){
    uint64_t a; asm("cvta.to.global.u64 %0, %1;":"=l"(a):"l"(p)); return a;
}
__device__ __forceinline__ void cp16(uint32_t dst, uint64_t src){
    asm volatile("cp.async.cg.shared.global [%0], [%1], 16;"::"r"(dst),"l"(src));
}
__device__ __forceinline__ uint2 f4_to_h4(float4 f){
    uint2 pk;
    pk.x = (uint32_t)__half_as_ushort(__float2half_rn(f.x)) |
           ((uint32_t)__half_as_ushort(__float2half_rn(f.y))<<16);
    pk.y = (uint32_t)__half_as_ushort(__float2half_rn(f.z)) |
           ((uint32_t)__half_as_ushort(__float2half_rn(f.w))<<16);
    return pk;
}
#define LDSM4(r0,r1,r2,r3,addr) \
    asm volatile("ldmatrix.sync.aligned.m8n8.x4.shared.b16 {%0,%1,%2,%3}, [%4];" \
        : "=r"(r0),"=r"(r1),"=r"(r2),"=r"(r3) : "r"(addr))
#define MMA(d,a,b0,b1) \
    asm volatile("mma.sync.aligned.m16n8k16.row.col.f32.f16.f16.f32 " \
        "{%0,%1,%2,%3}, {%4,%5,%6,%7}, {%8,%9}, {%0,%1,%2,%3};" \
        : "+f"((d)[0]),"+f"((d)[1]),"+f"((d)[2]),"+f"((d)[3]) \
        : "r"((a)[0]),"r"((a)[1]),"r"((a)[2]),"r"((a)[3]),"r"(b0),"r"(b1))

// ---- merged prep: A=[spk|z] fp16 (binary, exact); B=[Win|Wrec] fp16 ----
#define T_SPK (BDIM*(IN_F/4))            // 1048576
#define T_Z   (BDIM*(OUT_F/4))           // 2097152
#define T_WIN ((OUT_F*IN_F)/4)           // 131072
#define T_WRC ((OUT_F*OUT_F)/4)          // 262144
#define T_ALL (T_SPK+T_Z+T_WIN+T_WRC)

__global__ void prep_all(const float* __restrict__ spk, const float* __restrict__ zin,
                         const float* __restrict__ win, const float* __restrict__ wrec){
    int t = blockIdx.x*blockDim.x + threadIdx.x;
    if (t < T_SPK){
        int row = t>>7, c = (t&127)<<2;
        float4 f = *reinterpret_cast<const float4*>(spk + (size_t)row*IN_F + c);
        *reinterpret_cast<uint2*>(g_A + (size_t)row*K_TOT + c) = f4_to_h4(f);
    } else if (t < T_SPK + T_Z){
        int t2 = t - T_SPK;
        int row = t2>>8, c = (t2&255)<<2;
        float4 f = *reinterpret_cast<const float4*>(zin + (size_t)row*OUT_F + c);
        *reinterpret_cast<uint2*>(g_A + (size_t)row*K_TOT + IN_F + c) = f4_to_h4(f);
    } else if (t < T_SPK + T_Z + T_WIN){
        int t2 = t - (T_SPK + T_Z);
        int o = t2>>7, c = (t2&127)<<2;
        float4 f = *reinterpret_cast<const float4*>(win + (size_t)o*IN_F + c);
        *reinterpret_cast<uint2*>(g_B + (size_t)o*K_TOT + c) = f4_to_h4(f);
    } else {
        int t2 = t - (T_SPK + T_Z + T_WIN);
        if (t2 < T_WRC){
            int o = t2>>8, c = (t2&255)<<2;
            float4 f = *reinterpret_cast<const float4*>(wrec + (size_t)o*OUT_F + c);
            *reinterpret_cast<uint2*>(g_B + (size_t)o*K_TOT + IN_F + c) = f4_to_h4(f);
        }
    }
}

// 128-row x 128B-row tile loader, XOR-8 swizzle on 16B chunks
__device__ __forceinline__ void load_stage(uint32_t sA, uint32_t sB,
                                           uint64_t ga, uint64_t gb, int tid){
    const uint64_t gs = (uint64_t)K_TOT*2;
#pragma unroll
    for (int j = 0; j < 4; j++){
        int ch = tid + j*256, r = ch>>3, c = ch&7;
        uint32_t sw = (uint32_t)(r*128 + ((c ^ (r&7))<<4));
        cp16(sA + sw, ga + (uint64_t)r*gs + c*16);
    }
#pragma unroll
    for (int j = 0; j < 4; j++){
        int ch = tid + j*256, r = ch>>3, c = ch&7;
        uint32_t sw = (uint32_t)(r*128 + ((c ^ (r&7))<<4));
        cp16(sB + sw, gb + (uint64_t)r*gs + c*16);
    }
}

__global__ void __launch_bounds__(256, 2) lsnn_gemm(
    const float* __restrict__ vin, const float* __restrict__ iin,
    const float* __restrict__ bin, float* __restrict__ out)
{
    extern __shared__ char smem_raw[];
    const uint32_t s0 = (smem_u32(smem_raw) + 1023u) & ~1023u;
    const int tid = threadIdx.x, wid = tid>>5, lane = tid&31;
    const int wm = wid & 3, wn = wid >> 2;          // 4x2 warp grid: 32m x 64n each
    const int nt = blockIdx.x & 7, mt = blockIdx.x >> 3;
    const int m0 = mt*BM, n0 = nt*BN;

    const uint64_t gA0 = gaddr(g_A) + (uint64_t)m0*K_TOT*2;
    const uint64_t gB0 = gaddr(g_B) + (uint64_t)n0*K_TOT*2;

    float acc[2][8][4];
#pragma unroll
    for (int a = 0; a < 2; a++)
#pragma unroll
        for (int b = 0; b < 8; b++)
#pragma unroll
            for (int c = 0; c < 4; c++) acc[a][b][c] = 0.0f;

    // prologue: stages 0,1
#pragma unroll
    for (int i = 0; i < 2; i++){
        load_stage(s0 + i*STAGE_BYTES, s0 + SM_B_OFF + i*STAGE_BYTES,
                   gA0 + (uint64_t)i*BK*2, gB0 + (uint64_t)i*BK*2, tid);
        asm volatile("cp.async.commit_group;":::"memory");
    }

    const int rA = lane & 15, hi = lane >> 4;

    for (int i = 0; i < NIT; i++){
        // stage i arrived when <=1 newer group pending
        asm volatile("cp.async.wait_group 1;":::"memory");
        __syncthreads();   // publishes stage i; also frees stage (i-1)%3 for reuse

        // issue next loads BEFORE compute so they overlap the MMA block
        if (i + 2 < NIT){
            int s = (i+2)%3;
            load_stage(s0 + s*STAGE_BYTES, s0 + SM_B_OFF + s*STAGE_BYTES,
                       gA0 + (uint64_t)(i+2)*BK*2, gB0 + (uint64_t)(i+2)*BK*2, tid);
        }
        asm volatile("cp.async.commit_group;":::"memory");

        const uint32_t aB = s0 + (i%3)*STAGE_BYTES;
        const uint32_t bB = s0 + SM_B_OFF + (i%3)*STAGE_BYTES;
#pragma unroll
        for (int kk = 0; kk < 4; kk++){
            uint32_t a[2][4], b[4][4];
            const int ch = kk*2 + hi;
#pragma unroll
            for (int t = 0; t < 2; t++){
                int r = wm*32 + t*16 + rA;
                LDSM4(a[t][0],a[t][1],a[t][2],a[t][3],
                      aB + r*128 + ((ch ^ (r&7))<<4));
            }
#pragma unroll
            for (int t = 0; t < 4; t++){
                int r = wn*64 + t*16 + rA;
                LDSM4(b[t][0],b[t][1],b[t][2],b[t][3],
                      bB + r*128 + ((ch ^ (r&7))<<4));
            }
#pragma unroll
            for (int t = 0; t < 2; t++)
#pragma unroll
                for (int n8 = 0; n8 < 8; n8++)
                    MMA(acc[t][n8], a[t], b[n8>>1][n8&1], b[n8>>1][(n8&1)+2]);
        }
    }

    // ---- fused LSNN epilogue (exact reference op order; rn intrinsics) ----
    const float C_VD = 0.1f;
    const float C_ID = -0.2f;
    const float C_BD = 1.25e-6f;
    const float C_BJ = 0.00225f;
    const size_t PS = (size_t)BDIM*OUT_F;

#pragma unroll
    for (int t = 0; t < 2; t++){
#pragma unroll
        for (int rr = 0; rr < 2; rr++){
            const size_t row = (size_t)(m0 + wm*32 + t*16 + rr*8 + (lane>>2));
            const float* vr = vin + row*OUT_F;
            const float* ir = iin + row*OUT_F;
            const float* br = bin + row*OUT_F;
            float* oz = out + row*OUT_F;
#pragma unroll
            for (int n8 = 0; n8 < 8; n8++){
                const int c = n0 + wn*64 + n8*8 + 2*(lane&3);
                float2 v2 = *reinterpret_cast<const float2*>(vr + c);
                float2 i2 = *reinterpret_cast<const float2*>(ir + c);
                float2 b2 = *reinterpret_cast<const float2*>(br + c);
                float vv[2] = {v2.x, v2.y}, ii[2] = {i2.x, i2.y}, bb[2] = {b2.x, b2.y};
                float zz[2], vo[2], io[2], bo[2];
#pragma unroll
                for (int e = 0; e < 2; e++){
                    float vd = __fadd_rn(vv[e], __fmul_rn(C_VD, __fadd_rn(ii[e], -vv[e])));
                    float id = __fadd_rn(ii[e], __fmul_rn(C_ID, ii[e]));
                    float bd = __fadd_rn(bb[e], __fmul_rn(C_BD, __fadd_rn(1.0f, -bb[e])));
                    float zn = (__fadd_rn(vd, -bd) > 0.0f) ? 1.0f : 0.0f;
                    zz[e] = zn;
                    vo[e] = (zn != 0.0f) ? 0.0f : vd;
                    io[e] = __fadd_rn(id, acc[t][n8][rr*2 + e]);
                    bo[e] = __fadd_rn(bd, __fmul_rn(zn, C_BJ));
                }
                *reinterpret_cast<float2*>(oz + c)        = make_float2(zz[0], zz[1]);
                *reinterpret_cast<float2*>(oz + PS + c)   = make_float2(vo[0], vo[1]);
                *reinterpret_cast<float2*>(oz + 2*PS + c) = make_float2(io[0], io[1]);
                *reinterpret_cast<float2*>(oz + 3*PS + c) = make_float2(bo[0], bo[1]);
            }
        }
    }
}

extern "C" void kernel_launch(void* const* d_in, const int* in_sizes, int n_in,
                              void* d_out, int out_size){
    const float* spikes = (const float*)d_in[0];
    const float* z      = (const float*)d_in[1];
    const float* v      = (const float*)d_in[2];
    const float* i_     = (const float*)d_in[3];
    const float* b      = (const float*)d_in[4];
    const float* win    = (const float*)d_in[5];
    const float* wrec   = (const float*)d_in[6];
    float* out = (float*)d_out;

    cudaFuncSetAttribute(lsnn_gemm, cudaFuncAttributeMaxDynamicSharedMemorySize, SMEM_DYN);

    prep_all<<<(T_ALL + 255)/256, 256>>>(spikes, z, win, wrec);
    lsnn_gemm<<<(BDIM/BM)*(OUT_F/BN), 256, SMEM_DYN>>>(v, i_, b, out);
}